// round 6
// baseline (speedup 1.0000x reference)
#include <cuda_runtime.h>
#include <stdint.h>

// GCN graph classifier: 2x (GCNConv + ReLU) -> global_mean_pool -> Linear
// N=100k nodes, E=1.6M edges, H=128, G=512, OUT=2.
//
// R6 changes vs R5 (448us):
//  - FUSED agg1+GEMM2 kernel: each CTA aggregates its 128-node tile into
//    dynamic smem (bias+ReLU), then GEMMs that tile against W2. LTS-bound
//    aggregation overlaps FFMA-bound GEMM across CTAs; h never hits gmem.
//  - GEMM phase reads A directly from the smem h-tile (132-float padded
//    rows, 2-way-conflict scalar loads); only W double-buffered.
//  - buffers: GEMM1->g_xw; fused reads g_xw, writes g_h; agg2 reads g_h,
//    writes g_xw; pool reads g_xw.

#define HD   128
#define NMAX 100352
#define EMAX 1605632
#define HSTR 132            // padded smem row stride (floats)

__device__ __align__(16) float g_deg[NMAX];
__device__ __align__(16) float g_dis[NMAX];
__device__ __align__(16) int   g_row[EMAX];
__device__ __align__(16) int   g_col[EMAX];
__device__ __align__(16) int   g_batch[NMAX];
__device__ __align__(16) int   g_cnt[NMAX];
__device__ __align__(16) int   g_off[NMAX + 1];
__device__ __align__(16) int   g_cur[NMAX];
__device__ __align__(16) int   g_bsum[128];
__device__ __align__(16) int   g_bsumx[128];
__device__ __align__(16) int2  g_edge[EMAX];     // {src row, coef bits}
__device__ __align__(16) float g_xw[(size_t)NMAX * HD];
__device__ __align__(16) float g_h[(size_t)NMAX * HD];

// ---------------------------------------------------------------------------
// dtype detection (int64 arrays have zero hi-words at odd 32-bit indices)
// ---------------------------------------------------------------------------
__device__ __forceinline__ int detect_ei64(const int* ei32)
{
    int lane = threadIdx.x & 31;
    int v = ei32[2 * lane + 1];
    return __all_sync(0xffffffffu, v == 0);
}

__device__ __forceinline__ int detect_b64(const int* b32, int n)
{
    int lane = threadIdx.x & 31;
    int base = (n > 64) ? ((n - 64) & ~1) : 0;
    int v = b32[base + 2 * lane + 1];
    return __all_sync(0xffffffffu, v == 0);
}

// ---------------------------------------------------------------------------
// prep1: convert edge_index + batch, init deg/cnt
// ---------------------------------------------------------------------------
__global__ void k_prep1(const void* __restrict__ ei, const void* __restrict__ bt,
                        int n, int e)
{
    __shared__ int s_ei64, s_b64;
    const int* ei32 = (const int*)ei;
    const int* bt32 = (const int*)bt;
    int tid = threadIdx.x;
    if (tid < 32) {
        int r = detect_ei64(ei32);
        if (tid == 0) s_ei64 = r;
    } else if (tid < 64) {
        int r = detect_b64(bt32, n);
        if (tid == 32) s_b64 = r;
    }
    __syncthreads();

    int i = blockIdx.x * blockDim.x + tid;
    if (i < e) {
        if (s_ei64) {
            const long long* p = (const long long*)ei;
            g_row[i] = (int)p[i];
            g_col[i] = (int)p[(size_t)e + i];
        } else {
            g_row[i] = ei32[i];
            g_col[i] = ei32[e + i];
        }
    }
    if (i < n) {
        g_deg[i] = 1.0f;   // self-loop weight
        g_cnt[i] = 0;
        g_batch[i] = s_b64 ? (int)((const long long*)bt)[i] : bt32[i];
    }
}

__global__ void k_hist(const float* __restrict__ ew, int e)
{
    int i = blockIdx.x * blockDim.x + threadIdx.x;
    if (i >= e) return;
    int c = g_col[i];
    atomicAdd(&g_deg[c], ew[i]);
    atomicAdd(&g_cnt[c], 1);
}

// fused: blocks [0,nb) scan cnt within-block; blocks [nb,..) compute rsqrt(deg)
__global__ void k_scan_dis(int n, int nb)
{
    if ((int)blockIdx.x < nb) {
        __shared__ int s[1024];
        int i = blockIdx.x * 1024 + threadIdx.x;
        int v = (i < n) ? g_cnt[i] : 0;
        s[threadIdx.x] = v;
        __syncthreads();
        for (int off = 1; off < 1024; off <<= 1) {
            int t = 0;
            if ((int)threadIdx.x >= off) t = s[threadIdx.x - off];
            __syncthreads();
            if ((int)threadIdx.x >= off) s[threadIdx.x] += t;
            __syncthreads();
        }
        if (i < n) g_off[i] = s[threadIdx.x];
        if (threadIdx.x == 1023) g_bsum[blockIdx.x] = s[1023];
    } else {
        int i = (blockIdx.x - nb) * 1024 + threadIdx.x;
        if (i < n) g_dis[i] = rsqrtf(g_deg[i]);
    }
}

__global__ void k_scan2(int nb)
{
    __shared__ int s[1024];
    int t = threadIdx.x;
    int v = (t < nb) ? g_bsum[t] : 0;
    s[t] = v;
    __syncthreads();
    for (int off = 1; off < 1024; off <<= 1) {
        int u = 0;
        if (t >= off) u = s[t - off];
        __syncthreads();
        if (t >= off) s[t] += u;
        __syncthreads();
    }
    if (t < nb) g_bsumx[t] = s[t] - v;
}

__global__ void k_scan3(int n, int e)
{
    int i = blockIdx.x * blockDim.x + threadIdx.x;
    if (i < n) {
        int ex = g_off[i] - g_cnt[i] + g_bsumx[i >> 10];
        g_off[i] = ex;
        g_cur[i] = ex;
    }
    if (i == 0) g_off[n] = e;
}

__global__ void k_scatter(const float* __restrict__ ew, int e)
{
    int i = blockIdx.x * blockDim.x + threadIdx.x;
    if (i >= e) return;
    int r = g_row[i];
    int c = g_col[i];
    float coef = g_dis[r] * ew[i] * g_dis[c];
    int slot = atomicAdd(&g_cur[c], 1);
    g_edge[slot] = make_int2(r, __float_as_int(coef));
}

// ---------------------------------------------------------------------------
// aggregation core: acc = selfc*src[node] + sum coef*src[edge.src], +bias, relu
// ---------------------------------------------------------------------------
__device__ __forceinline__ float4 agg_node(const float4* __restrict__ src4,
                                           int node, int lane, float4 bb)
{
    float sc = g_dis[node];
    float4 acc = src4[(size_t)node * 32 + lane];
    float s2 = sc * sc;
    acc.x *= s2; acc.y *= s2; acc.z *= s2; acc.w *= s2;

    int p  = g_off[node];
    int p1 = g_off[node + 1];
    for (; p + 3 < p1; p += 4) {
        int2 e0 = g_edge[p];
        int2 e1 = g_edge[p + 1];
        int2 e2 = g_edge[p + 2];
        int2 e3 = g_edge[p + 3];
        float4 u0 = src4[(size_t)e0.x * 32 + lane];
        float4 u1 = src4[(size_t)e1.x * 32 + lane];
        float4 u2 = src4[(size_t)e2.x * 32 + lane];
        float4 u3 = src4[(size_t)e3.x * 32 + lane];
        float c0 = __int_as_float(e0.y);
        float c1 = __int_as_float(e1.y);
        float c2 = __int_as_float(e2.y);
        float c3 = __int_as_float(e3.y);
        acc.x += c0 * u0.x + c1 * u1.x + c2 * u2.x + c3 * u3.x;
        acc.y += c0 * u0.y + c1 * u1.y + c2 * u2.y + c3 * u3.y;
        acc.z += c0 * u0.z + c1 * u1.z + c2 * u2.z + c3 * u3.z;
        acc.w += c0 * u0.w + c1 * u1.w + c2 * u2.w + c3 * u3.w;
    }
    for (; p < p1; p++) {
        int2 e0 = g_edge[p];
        float4 u0 = src4[(size_t)e0.x * 32 + lane];
        float c0 = __int_as_float(e0.y);
        acc.x += c0 * u0.x;
        acc.y += c0 * u0.y;
        acc.z += c0 * u0.z;
        acc.w += c0 * u0.w;
    }
    float4 o;
    o.x = fmaxf(acc.x + bb.x, 0.0f);
    o.y = fmaxf(acc.y + bb.y, 0.0f);
    o.z = fmaxf(acc.z + bb.z, 0.0f);
    o.w = fmaxf(acc.w + bb.w, 0.0f);
    return o;
}

// ---------------------------------------------------------------------------
// standalone SGEMM (layer 1): g_xw = Xin @ W
// ---------------------------------------------------------------------------
__global__ void __launch_bounds__(256, 2) k_gemm(const float* __restrict__ Xin,
                                                 const float* __restrict__ W,
                                                 int n)
{
    __shared__ __align__(16) float As[2][8][128];
    __shared__ __align__(16) float Ws[2][8][128];

    float* C = g_xw;
    int tid = threadIdx.x;
    int tx = tid & 15;
    int ty = tid >> 4;
    int m0 = ty * 8;
    int n0 = tx * 8;
    int rowBase = blockIdx.x * 128;

    int lr = tid >> 1;
    int kp = (tid & 1) * 4;
    int arow = min(rowBase + lr, n - 1);
    const float* aptr = Xin + (size_t)arow * HD + kp;
    int wk = (tid * 4) >> 7;
    int wn = (tid * 4) & 127;
    const float* wptr = W + (size_t)wk * HD + wn;

    float4 av = *(const float4*)aptr;
    float4 wv = *(const float4*)wptr;
    As[0][kp + 0][lr] = av.x;
    As[0][kp + 1][lr] = av.y;
    As[0][kp + 2][lr] = av.z;
    As[0][kp + 3][lr] = av.w;
    *(float4*)&Ws[0][wk][wn] = wv;
    __syncthreads();

    float acc[8][8];
#pragma unroll
    for (int i = 0; i < 8; i++)
#pragma unroll
        for (int j = 0; j < 8; j++) acc[i][j] = 0.0f;

#pragma unroll
    for (int kc = 0; kc < 16; kc++) {
        int cur = kc & 1;
        int nxt = cur ^ 1;
        if (kc < 15) {
            av = *(const float4*)(aptr + (kc + 1) * 8);
            wv = *(const float4*)(wptr + (size_t)(kc + 1) * 8 * HD);
        }
#pragma unroll
        for (int k = 0; k < 8; k++) {
            float a[8], w[8];
            *(float4*)&a[0] = *(const float4*)&As[cur][k][m0];
            *(float4*)&a[4] = *(const float4*)&As[cur][k][m0 + 4];
            *(float4*)&w[0] = *(const float4*)&Ws[cur][k][n0];
            *(float4*)&w[4] = *(const float4*)&Ws[cur][k][n0 + 4];
#pragma unroll
            for (int i = 0; i < 8; i++)
#pragma unroll
                for (int j = 0; j < 8; j++)
                    acc[i][j] += a[i] * w[j];
        }
        if (kc < 15) {
            As[nxt][kp + 0][lr] = av.x;
            As[nxt][kp + 1][lr] = av.y;
            As[nxt][kp + 2][lr] = av.z;
            As[nxt][kp + 3][lr] = av.w;
            *(float4*)&Ws[nxt][wk][wn] = wv;
        }
        __syncthreads();
    }

#pragma unroll
    for (int i = 0; i < 8; i++) {
        int r = rowBase + m0 + i;
        if (r < n) {
            *(float4*)(C + (size_t)r * HD + n0) =
                make_float4(acc[i][0], acc[i][1], acc[i][2], acc[i][3]);
            *(float4*)(C + (size_t)r * HD + n0 + 4) =
                make_float4(acc[i][4], acc[i][5], acc[i][6], acc[i][7]);
        }
    }
}

// ---------------------------------------------------------------------------
// FUSED agg1 + GEMM2: per CTA, aggregate 128 nodes from g_xw into smem
// h-tile (bias1 + ReLU), then GEMM h_tile @ W2 -> g_h rows.
// dyn smem: h_s[128*HSTR] + Ws[2*8*128]
// ---------------------------------------------------------------------------
__global__ void __launch_bounds__(256, 2) k_agg_gemm(const float* __restrict__ bias,
                                                     const float* __restrict__ W,
                                                     int n)
{
    extern __shared__ __align__(16) float sm[];
    float* h_s = sm;                        // [128][HSTR]
    float* Ws  = sm + 128 * HSTR;           // [2][8][128]

    int tid = threadIdx.x;
    int lane = tid & 31;
    int w = tid >> 5;
    int rowBase = blockIdx.x * 128;
    const float4* x4 = (const float4*)g_xw;
    float4 bb = ((const float4*)bias)[lane];

    // ---- phase A: aggregate 16 nodes per warp into smem tile ----
    for (int j = 0; j < 16; j++) {
        int local = w * 16 + j;
        int node = rowBase + local;
        float4 o = make_float4(0.f, 0.f, 0.f, 0.f);
        if (node < n) o = agg_node(x4, node, lane, bb);
        *(float4*)&h_s[(size_t)local * HSTR + 4 * lane] = o;
    }

    // stage W chunk 0 (store before the phase sync; covered by it)
    int tx = tid & 15;
    int ty = tid >> 4;
    int m0 = ty * 8;
    int n0 = tx * 8;
    int wk = (tid * 4) >> 7;
    int wn = (tid * 4) & 127;
    const float* wptr = W + (size_t)wk * HD + wn;
    float4 wv = *(const float4*)wptr;
    *(float4*)&Ws[(0 * 8 + wk) * 128 + wn] = wv;
    __syncthreads();

    // ---- phase B: GEMM h_s @ W -> g_h ----
    float acc[8][8];
#pragma unroll
    for (int i = 0; i < 8; i++)
#pragma unroll
        for (int j = 0; j < 8; j++) acc[i][j] = 0.0f;

#pragma unroll
    for (int kc = 0; kc < 16; kc++) {
        int cur = kc & 1;
        int nxt = cur ^ 1;
        if (kc < 15)
            wv = *(const float4*)(wptr + (size_t)(kc + 1) * 8 * HD);
#pragma unroll
        for (int k = 0; k < 8; k++) {
            int kk = kc * 8 + k;
            float a[8], ww[8];
#pragma unroll
            for (int i = 0; i < 8; i++)
                a[i] = h_s[(size_t)(m0 + i) * HSTR + kk];
            *(float4*)&ww[0] = *(const float4*)&Ws[(cur * 8 + k) * 128 + n0];
            *(float4*)&ww[4] = *(const float4*)&Ws[(cur * 8 + k) * 128 + n0 + 4];
#pragma unroll
            for (int i = 0; i < 8; i++)
#pragma unroll
                for (int j = 0; j < 8; j++)
                    acc[i][j] += a[i] * ww[j];
        }
        if (kc < 15)
            *(float4*)&Ws[(nxt * 8 + wk) * 128 + wn] = wv;
        __syncthreads();
    }

#pragma unroll
    for (int i = 0; i < 8; i++) {
        int r = rowBase + m0 + i;
        if (r < n) {
            *(float4*)(g_h + (size_t)r * HD + n0) =
                make_float4(acc[i][0], acc[i][1], acc[i][2], acc[i][3]);
            *(float4*)(g_h + (size_t)r * HD + n0 + 4) =
                make_float4(acc[i][4], acc[i][5], acc[i][6], acc[i][7]);
        }
    }
}

// ---------------------------------------------------------------------------
// standalone aggregation (layer 2): g_xw[node] = relu-agg over g_h
// ---------------------------------------------------------------------------
__global__ void k_agg2(const float* __restrict__ bias, int n)
{
    int gw = (blockIdx.x * blockDim.x + threadIdx.x) >> 5;
    int lane = threadIdx.x & 31;
    if (gw >= n) return;
    float4 bb = ((const float4*)bias)[lane];
    float4 o = agg_node((const float4*)g_h, gw, lane, bb);
    ((float4*)g_xw)[(size_t)gw * 32 + lane] = o;
}

// ---------------------------------------------------------------------------
// fused pooling + classifier over g_xw (binary-search graph bounds)
// ---------------------------------------------------------------------------
__global__ void k_poolfinal(const float* __restrict__ Wl, const float* __restrict__ bl,
                            float* __restrict__ out, int n)
{
    int g = blockIdx.x;
    int f = threadIdx.x;
    __shared__ int sb[2];
    __shared__ float r0[128], r1[128];

    if (f < 2) {
        int target = g + f;
        int lo = 0, hi = n;
        while (lo < hi) {
            int mid = (lo + hi) >> 1;
            if (g_batch[mid] < target) lo = mid + 1; else hi = mid;
        }
        sb[f] = lo;
    }
    __syncthreads();
    int s = sb[0], t = sb[1];

    float acc = 0.0f;
    for (int i = s; i < t; i++) acc += g_xw[(size_t)i * HD + f];
    float pooled = acc / fmaxf((float)(t - s), 1.0f);

    r0[f] = pooled * Wl[f * 2 + 0];
    r1[f] = pooled * Wl[f * 2 + 1];
    __syncthreads();
#pragma unroll
    for (int off = 64; off > 0; off >>= 1) {
        if (f < off) { r0[f] += r0[f + off]; r1[f] += r1[f + off]; }
        __syncthreads();
    }
    if (f == 0) {
        out[g * 2 + 0] = r0[0] + bl[0];
        out[g * 2 + 1] = r1[0] + bl[1];
    }
}

// ---------------------------------------------------------------------------
static inline int ceil_div_i(int a, int b) { return (a + b - 1) / b; }

extern "C" void kernel_launch(void* const* d_in, const int* in_sizes, int n_in,
                              void* d_out, int out_size)
{
    (void)n_in;
    const float* x  = (const float*)d_in[0];
    const void*  ei = d_in[1];
    const float* ew = (const float*)d_in[2];
    const void*  bt = d_in[3];
    const float* W1 = (const float*)d_in[4];
    const float* b1 = (const float*)d_in[5];
    const float* W2 = (const float*)d_in[6];
    const float* b2 = (const float*)d_in[7];
    const float* Wl = (const float*)d_in[8];
    const float* bl = (const float*)d_in[9];
    float* out = (float*)d_out;

    int n = in_sizes[0] / HD;
    int e = in_sizes[2];
    int G = out_size / 2;

    int eb = ceil_div_i(e, 256);
    int nb = ceil_div_i(n, 1024);
    int gemm_blocks = ceil_div_i(n, 128);
    int agg_blocks  = ceil_div_i(n, 8);

    // dynamic smem for fused kernel: h tile + W double buffer
    int fused_smem = (128 * HSTR + 2 * 8 * 128) * (int)sizeof(float);
    cudaFuncSetAttribute(k_agg_gemm, cudaFuncAttributeMaxDynamicSharedMemorySize,
                         fused_smem);

    // fork side stream: GEMM1 (depends only on x) overlaps CSR build
    cudaStream_t s2 = 0;
    cudaEvent_t evA = 0, evB = 0;
    bool forked = false;
    if (cudaStreamCreateWithFlags(&s2, cudaStreamNonBlocking) == cudaSuccess &&
        cudaEventCreateWithFlags(&evA, cudaEventDisableTiming) == cudaSuccess &&
        cudaEventCreateWithFlags(&evB, cudaEventDisableTiming) == cudaSuccess) {
        if (cudaEventRecord(evA, 0) == cudaSuccess &&
            cudaStreamWaitEvent(s2, evA, 0) == cudaSuccess)
            forked = true;
    }

    cudaStream_t gs = forked ? s2 : (cudaStream_t)0;
    k_gemm<<<gemm_blocks, 256, 0, gs>>>(x, W1, n);
    if (forked) cudaEventRecord(evB, s2);

    // CSR build chain on main stream
    k_prep1<<<eb, 256>>>(ei, bt, n, e);
    k_hist<<<eb, 256>>>(ew, e);
    k_scan_dis<<<nb + ceil_div_i(n, 1024), 1024>>>(n, nb);
    k_scan2<<<1, 1024>>>(nb);
    k_scan3<<<ceil_div_i(n, 256), 256>>>(n, e);
    k_scatter<<<eb, 256>>>(ew, e);

    if (forked) cudaStreamWaitEvent(0, evB, 0);

    // fused layer-1 aggregation + layer-2 GEMM, then layer-2 aggregation
    k_agg_gemm<<<gemm_blocks, 256, fused_smem>>>(b1, W2, n);
    k_agg2<<<agg_blocks, 256>>>(b2, n);

    // pooling + classifier
    k_poolfinal<<<G, 128>>>(Wl, bl, out, n);
}

// round 7
// speedup vs baseline: 1.6073x; 1.6073x over previous
#include <cuda_runtime.h>
#include <cuda_bf16.h>
#include <stdint.h>

// GCN graph classifier: 2x (GCNConv + ReLU) -> global_mean_pool -> Linear
// N=100k, E=1.6M, H=128, G=512, OUT=2.
//
// R7 vs R5 (448us best; R6 fusion regressed and is reverted):
//  - GEMMs via split-bf16 tensor cores: x = hi+lo (bf16), x@W =
//    hi@Whi + hi@Wlo + lo@Whi with mma.sync.m16n8k16 f32 accumulators.
//    W pre-split + transposed once into device globals.
//  - k_hist fused into k_prep1 (k_init runs first to avoid the init race)
//  - fork/join: wsplit+GEMM1 on side stream overlap the CSR build chain

#define HD   128
#define NMAX 100352
#define EMAX 1605632
#define WPAD 136          // padded k-stride (bf16 elems) for smem tiles

__device__ __align__(16) float g_deg[NMAX];
__device__ __align__(16) float g_dis[NMAX];
__device__ __align__(16) int   g_row[EMAX];
__device__ __align__(16) int   g_col[EMAX];
__device__ __align__(16) int   g_batch[NMAX];
__device__ __align__(16) int   g_cnt[NMAX];
__device__ __align__(16) int   g_off[NMAX + 1];
__device__ __align__(16) int   g_cur[NMAX];
__device__ __align__(16) int   g_bsum[128];
__device__ __align__(16) int   g_bsumx[128];
__device__ __align__(16) int2  g_edge[EMAX];        // {src row, coef bits}
__device__ __align__(16) float g_xw[(size_t)NMAX * HD];   // GEMM outputs
__device__ __align__(16) float g_h[(size_t)NMAX * HD];    // agg outputs
__device__ __align__(16) __nv_bfloat16 g_Wh[2][HD * HD];  // W^T hi, [n][k]
__device__ __align__(16) __nv_bfloat16 g_Wl[2][HD * HD];  // W^T lo

// ---------------------------------------------------------------------------
// dtype detection (int64 arrays have zero hi-words at odd 32-bit indices)
// ---------------------------------------------------------------------------
__device__ __forceinline__ int detect_ei64(const int* ei32)
{
    int lane = threadIdx.x & 31;
    int v = ei32[2 * lane + 1];
    return __all_sync(0xffffffffu, v == 0);
}

__device__ __forceinline__ int detect_b64(const int* b32, int n)
{
    int lane = threadIdx.x & 31;
    int base = (n > 64) ? ((n - 64) & ~1) : 0;
    int v = b32[base + 2 * lane + 1];
    return __all_sync(0xffffffffu, v == 0);
}

// ---------------------------------------------------------------------------
__global__ void k_init(int n)
{
    int i = blockIdx.x * blockDim.x + threadIdx.x;
    if (i < n) { g_deg[i] = 0.0f; g_cnt[i] = 0; }
}

// prep1: convert edge_index + batch, and fused histogram/degree atomics
__global__ void k_prep1(const void* __restrict__ ei, const void* __restrict__ bt,
                        const float* __restrict__ ew, int n, int e)
{
    __shared__ int s_ei64, s_b64;
    const int* ei32 = (const int*)ei;
    const int* bt32 = (const int*)bt;
    int tid = threadIdx.x;
    if (tid < 32) {
        int r = detect_ei64(ei32);
        if (tid == 0) s_ei64 = r;
    } else if (tid < 64) {
        int r = detect_b64(bt32, n);
        if (tid == 32) s_b64 = r;
    }
    __syncthreads();

    int i = blockIdx.x * blockDim.x + tid;
    if (i < e) {
        int r, c;
        if (s_ei64) {
            const long long* p = (const long long*)ei;
            r = (int)p[i];
            c = (int)p[(size_t)e + i];
        } else {
            r = ei32[i];
            c = ei32[e + i];
        }
        g_row[i] = r;
        g_col[i] = c;
        atomicAdd(&g_deg[c], ew[i]);
        atomicAdd(&g_cnt[c], 1);
    }
    if (i < n)
        g_batch[i] = s_b64 ? (int)((const long long*)bt)[i] : bt32[i];
}

// fused: blocks [0,nb) scan cnt within-block; blocks [nb,..) rsqrt(deg+1)
__global__ void k_scan_dis(int n, int nb)
{
    if ((int)blockIdx.x < nb) {
        __shared__ int s[1024];
        int i = blockIdx.x * 1024 + threadIdx.x;
        int v = (i < n) ? g_cnt[i] : 0;
        s[threadIdx.x] = v;
        __syncthreads();
        for (int off = 1; off < 1024; off <<= 1) {
            int t = 0;
            if ((int)threadIdx.x >= off) t = s[threadIdx.x - off];
            __syncthreads();
            if ((int)threadIdx.x >= off) s[threadIdx.x] += t;
            __syncthreads();
        }
        if (i < n) g_off[i] = s[threadIdx.x];
        if (threadIdx.x == 1023) g_bsum[blockIdx.x] = s[1023];
    } else {
        int i = (blockIdx.x - nb) * 1024 + threadIdx.x;
        if (i < n) g_dis[i] = rsqrtf(g_deg[i] + 1.0f);   // +1 = self-loop
    }
}

__global__ void k_scan2(int nb)
{
    __shared__ int s[1024];
    int t = threadIdx.x;
    int v = (t < nb) ? g_bsum[t] : 0;
    s[t] = v;
    __syncthreads();
    for (int off = 1; off < 1024; off <<= 1) {
        int u = 0;
        if (t >= off) u = s[t - off];
        __syncthreads();
        if (t >= off) s[t] += u;
        __syncthreads();
    }
    if (t < nb) g_bsumx[t] = s[t] - v;
}

__global__ void k_scan3(int n, int e)
{
    int i = blockIdx.x * blockDim.x + threadIdx.x;
    if (i < n) {
        int ex = g_off[i] - g_cnt[i] + g_bsumx[i >> 10];
        g_off[i] = ex;
        g_cur[i] = ex;
    }
    if (i == 0) g_off[n] = e;
}

__global__ void k_scatter(const float* __restrict__ ew, int e)
{
    int i = blockIdx.x * blockDim.x + threadIdx.x;
    if (i >= e) return;
    int r = g_row[i];
    int c = g_col[i];
    float coef = g_dis[r] * ew[i] * g_dis[c];
    int slot = atomicAdd(&g_cur[c], 1);
    g_edge[slot] = make_int2(r, __float_as_int(coef));
}

// ---------------------------------------------------------------------------
// W split: W[k][n] fp32 -> transposed bf16 hi/lo [n][k]
// ---------------------------------------------------------------------------
__global__ void k_wsplit(const float* __restrict__ W1, const float* __restrict__ W2)
{
    int idx = blockIdx.x * blockDim.x + threadIdx.x;
    if (idx >= HD * HD) return;
    int k = idx >> 7, nn = idx & 127;
    float w1 = W1[idx], w2 = W2[idx];
    __nv_bfloat16 h1 = __float2bfloat16(w1);
    __nv_bfloat16 h2 = __float2bfloat16(w2);
    int o = nn * HD + k;
    g_Wh[0][o] = h1;
    g_Wl[0][o] = __float2bfloat16(w1 - __bfloat162float(h1));
    g_Wh[1][o] = h2;
    g_Wl[1][o] = __float2bfloat16(w2 - __bfloat162float(h2));
}

// ---------------------------------------------------------------------------
// tensor-core GEMM: g_xw[n x 128] = A[n x 128] @ W  (split-bf16, 3 mma terms)
// CTA: 256 thr = 8 warps, tile 128m x 128n, warp tile 64m x 32n, K=128 staged.
// ---------------------------------------------------------------------------
#define MMA16816(d, a, b)                                                     \
    asm volatile("mma.sync.aligned.m16n8k16.row.col.f32.bf16.bf16.f32 "       \
                 "{%0,%1,%2,%3}, {%4,%5,%6,%7}, {%8,%9}, {%0,%1,%2,%3};"      \
                 : "+f"((d)[0]), "+f"((d)[1]), "+f"((d)[2]), "+f"((d)[3])     \
                 : "r"((a)[0]), "r"((a)[1]), "r"((a)[2]), "r"((a)[3]),        \
                   "r"((b)[0]), "r"((b)[1]))

__global__ void __launch_bounds__(256) k_gemm_tc(const float* __restrict__ Xin,
                                                 int widx, int useH, int n)
{
    extern __shared__ __align__(16) char smraw[];
    __nv_bfloat16* Ah = (__nv_bfloat16*)smraw;       // [128][WPAD]
    __nv_bfloat16* Al = Ah + 128 * WPAD;
    __nv_bfloat16* Bh = Al + 128 * WPAD;             // W^T [n][k], [128][WPAD]
    __nv_bfloat16* Bl = Bh + 128 * WPAD;

    const float* A = useH ? (const float*)g_h : Xin;
    int tid = threadIdx.x;
    int rowBase = blockIdx.x * 128;

    // stage + split A tile (4096 float4, 16 per thread)
#pragma unroll
    for (int i = 0; i < 16; i++) {
        int f4 = tid + i * 256;
        int r = f4 >> 5;
        int c4 = (f4 & 31) * 4;
        int ar = min(rowBase + r, n - 1);
        float4 v = *(const float4*)(A + (size_t)ar * HD + c4);
        __nv_bfloat16 hx = __float2bfloat16(v.x);
        __nv_bfloat16 hy = __float2bfloat16(v.y);
        __nv_bfloat16 hz = __float2bfloat16(v.z);
        __nv_bfloat16 hw = __float2bfloat16(v.w);
        __nv_bfloat16 lx = __float2bfloat16(v.x - __bfloat162float(hx));
        __nv_bfloat16 ly = __float2bfloat16(v.y - __bfloat162float(hy));
        __nv_bfloat16 lz = __float2bfloat16(v.z - __bfloat162float(hz));
        __nv_bfloat16 lw = __float2bfloat16(v.w - __bfloat162float(hw));
        __nv_bfloat162 h01, h23, l01, l23;
        h01.x = hx; h01.y = hy; h23.x = hz; h23.y = hw;
        l01.x = lx; l01.y = ly; l23.x = lz; l23.y = lw;
        uint2 uh, ul;
        uh.x = *(uint32_t*)&h01; uh.y = *(uint32_t*)&h23;
        ul.x = *(uint32_t*)&l01; ul.y = *(uint32_t*)&l23;
        *(uint2*)&Ah[r * WPAD + c4] = uh;
        *(uint2*)&Al[r * WPAD + c4] = ul;
    }

    // stage W^T tiles (bf16, 8 elems per uint4, 8 iters per thread)
#pragma unroll
    for (int i = 0; i < 8; i++) {
        int idx8 = (tid + i * 256) * 8;
        int r = idx8 >> 7;
        int c = idx8 & 127;
        *(uint4*)&Bh[r * WPAD + c] = *(const uint4*)&g_Wh[widx][idx8];
        *(uint4*)&Bl[r * WPAD + c] = *(const uint4*)&g_Wl[widx][idx8];
    }
    __syncthreads();

    int lane = tid & 31;
    int w = tid >> 5;
    int g = lane >> 2;
    int t = lane & 3;
    int wm0 = (w & 1) * 64;
    int wn0 = (w >> 1) * 32;

    float acc[4][4][4];
#pragma unroll
    for (int mb = 0; mb < 4; mb++)
#pragma unroll
        for (int nb = 0; nb < 4; nb++)
#pragma unroll
            for (int q = 0; q < 4; q++) acc[mb][nb][q] = 0.0f;

#pragma unroll
    for (int ks = 0; ks < 8; ks++) {
        int k0 = ks * 16 + t * 2;
        uint32_t ah[4][4], al[4][4];
#pragma unroll
        for (int mb = 0; mb < 4; mb++) {
            int r0 = wm0 + mb * 16 + g;
            ah[mb][0] = *(const uint32_t*)&Ah[r0 * WPAD + k0];
            ah[mb][1] = *(const uint32_t*)&Ah[(r0 + 8) * WPAD + k0];
            ah[mb][2] = *(const uint32_t*)&Ah[r0 * WPAD + k0 + 8];
            ah[mb][3] = *(const uint32_t*)&Ah[(r0 + 8) * WPAD + k0 + 8];
            al[mb][0] = *(const uint32_t*)&Al[r0 * WPAD + k0];
            al[mb][1] = *(const uint32_t*)&Al[(r0 + 8) * WPAD + k0];
            al[mb][2] = *(const uint32_t*)&Al[r0 * WPAD + k0 + 8];
            al[mb][3] = *(const uint32_t*)&Al[(r0 + 8) * WPAD + k0 + 8];
        }
        uint32_t bh[4][2], bl[4][2];
#pragma unroll
        for (int nb = 0; nb < 4; nb++) {
            int nr = wn0 + nb * 8 + g;
            bh[nb][0] = *(const uint32_t*)&Bh[nr * WPAD + k0];
            bh[nb][1] = *(const uint32_t*)&Bh[nr * WPAD + k0 + 8];
            bl[nb][0] = *(const uint32_t*)&Bl[nr * WPAD + k0];
            bl[nb][1] = *(const uint32_t*)&Bl[nr * WPAD + k0 + 8];
        }
#pragma unroll
        for (int mb = 0; mb < 4; mb++)
#pragma unroll
            for (int nb = 0; nb < 4; nb++) {
                MMA16816(acc[mb][nb], ah[mb], bh[nb]);
                MMA16816(acc[mb][nb], ah[mb], bl[nb]);
                MMA16816(acc[mb][nb], al[mb], bh[nb]);
            }
    }

    // write C
#pragma unroll
    for (int mb = 0; mb < 4; mb++) {
#pragma unroll
        for (int nb = 0; nb < 4; nb++) {
            int r0 = rowBase + wm0 + mb * 16 + g;
            int c0 = wn0 + nb * 8 + t * 2;
            if (r0 < n) {
                float2 v0 = make_float2(acc[mb][nb][0], acc[mb][nb][1]);
                *(float2*)&g_xw[(size_t)r0 * HD + c0] = v0;
            }
            if (r0 + 8 < n) {
                float2 v1 = make_float2(acc[mb][nb][2], acc[mb][nb][3]);
                *(float2*)&g_xw[(size_t)(r0 + 8) * HD + c0] = v1;
            }
        }
    }
}

// ---------------------------------------------------------------------------
// aggregation: g_h[node] = relu( dis^2*g_xw[node] + sum coef*g_xw[src] + b )
// warp per node, float4 lane slices, no atomics
// ---------------------------------------------------------------------------
__global__ void k_agg(const float* __restrict__ bias, int n)
{
    int gw = (blockIdx.x * blockDim.x + threadIdx.x) >> 5;
    int lane = threadIdx.x & 31;
    if (gw >= n) return;

    const float4* x4 = (const float4*)g_xw;
    float sc = g_dis[gw];
    float4 acc = x4[(size_t)gw * 32 + lane];
    float s2 = sc * sc;
    acc.x *= s2; acc.y *= s2; acc.z *= s2; acc.w *= s2;

    int p  = g_off[gw];
    int p1 = g_off[gw + 1];
    for (; p + 3 < p1; p += 4) {
        int2 e0 = g_edge[p];
        int2 e1 = g_edge[p + 1];
        int2 e2 = g_edge[p + 2];
        int2 e3 = g_edge[p + 3];
        float4 u0 = x4[(size_t)e0.x * 32 + lane];
        float4 u1 = x4[(size_t)e1.x * 32 + lane];
        float4 u2 = x4[(size_t)e2.x * 32 + lane];
        float4 u3 = x4[(size_t)e3.x * 32 + lane];
        float c0 = __int_as_float(e0.y);
        float c1 = __int_as_float(e1.y);
        float c2 = __int_as_float(e2.y);
        float c3 = __int_as_float(e3.y);
        acc.x += c0 * u0.x + c1 * u1.x + c2 * u2.x + c3 * u3.x;
        acc.y += c0 * u0.y + c1 * u1.y + c2 * u2.y + c3 * u3.y;
        acc.z += c0 * u0.z + c1 * u1.z + c2 * u2.z + c3 * u3.z;
        acc.w += c0 * u0.w + c1 * u1.w + c2 * u2.w + c3 * u3.w;
    }
    for (; p < p1; p++) {
        int2 e0 = g_edge[p];
        float4 u0 = x4[(size_t)e0.x * 32 + lane];
        float c0 = __int_as_float(e0.y);
        acc.x += c0 * u0.x;
        acc.y += c0 * u0.y;
        acc.z += c0 * u0.z;
        acc.w += c0 * u0.w;
    }

    float4 bb = ((const float4*)bias)[lane];
    float4 o;
    o.x = fmaxf(acc.x + bb.x, 0.0f);
    o.y = fmaxf(acc.y + bb.y, 0.0f);
    o.z = fmaxf(acc.z + bb.z, 0.0f);
    o.w = fmaxf(acc.w + bb.w, 0.0f);
    ((float4*)g_h)[(size_t)gw * 32 + lane] = o;
}

// ---------------------------------------------------------------------------
// fused pooling + classifier over g_h (binary-search graph bounds)
// ---------------------------------------------------------------------------
__global__ void k_poolfinal(const float* __restrict__ Wl, const float* __restrict__ bl,
                            float* __restrict__ out, int n)
{
    int g = blockIdx.x;
    int f = threadIdx.x;
    __shared__ int sb[2];
    __shared__ float r0[128], r1[128];

    if (f < 2) {
        int target = g + f;
        int lo = 0, hi = n;
        while (lo < hi) {
            int mid = (lo + hi) >> 1;
            if (g_batch[mid] < target) lo = mid + 1; else hi = mid;
        }
        sb[f] = lo;
    }
    __syncthreads();
    int s = sb[0], t = sb[1];

    float acc = 0.0f;
    for (int i = s; i < t; i++) acc += g_h[(size_t)i * HD + f];
    float pooled = acc / fmaxf((float)(t - s), 1.0f);

    r0[f] = pooled * Wl[f * 2 + 0];
    r1[f] = pooled * Wl[f * 2 + 1];
    __syncthreads();
#pragma unroll
    for (int off = 64; off > 0; off >>= 1) {
        if (f < off) { r0[f] += r0[f + off]; r1[f] += r1[f + off]; }
        __syncthreads();
    }
    if (f == 0) {
        out[g * 2 + 0] = r0[0] + bl[0];
        out[g * 2 + 1] = r1[0] + bl[1];
    }
}

// ---------------------------------------------------------------------------
static inline int ceil_div_i(int a, int b) { return (a + b - 1) / b; }

extern "C" void kernel_launch(void* const* d_in, const int* in_sizes, int n_in,
                              void* d_out, int out_size)
{
    (void)n_in;
    const float* x  = (const float*)d_in[0];
    const void*  ei = d_in[1];
    const float* ew = (const float*)d_in[2];
    const void*  bt = d_in[3];
    const float* W1 = (const float*)d_in[4];
    const float* b1 = (const float*)d_in[5];
    const float* W2 = (const float*)d_in[6];
    const float* b2 = (const float*)d_in[7];
    const float* Wl = (const float*)d_in[8];
    const float* bl = (const float*)d_in[9];
    float* out = (float*)d_out;

    int n = in_sizes[0] / HD;
    int e = in_sizes[2];
    int G = out_size / 2;

    int eb = ceil_div_i(e, 256);
    int nb = ceil_div_i(n, 1024);
    int gemm_blocks = ceil_div_i(n, 128);
    int agg_blocks  = ceil_div_i(n, 8);

    int gemm_smem = 4 * 128 * WPAD * (int)sizeof(__nv_bfloat16);  // 139264
    cudaFuncSetAttribute(k_gemm_tc, cudaFuncAttributeMaxDynamicSharedMemorySize,
                         gemm_smem);

    // k_init must precede the fused hist atomics in k_prep1
    k_init<<<ceil_div_i(n, 256), 256>>>(n);

    // fork side stream: wsplit + GEMM1 overlap the CSR build chain
    cudaStream_t s2 = 0;
    cudaEvent_t evA = 0, evB = 0;
    bool forked = false;
    if (cudaStreamCreateWithFlags(&s2, cudaStreamNonBlocking) == cudaSuccess &&
        cudaEventCreateWithFlags(&evA, cudaEventDisableTiming) == cudaSuccess &&
        cudaEventCreateWithFlags(&evB, cudaEventDisableTiming) == cudaSuccess) {
        if (cudaEventRecord(evA, 0) == cudaSuccess &&
            cudaStreamWaitEvent(s2, evA, 0) == cudaSuccess)
            forked = true;
    }

    cudaStream_t gs = forked ? s2 : (cudaStream_t)0;
    k_wsplit<<<ceil_div_i(HD * HD, 256), 256, 0, gs>>>(W1, W2);
    k_gemm_tc<<<gemm_blocks, 256, gemm_smem, gs>>>(x, 0, 0, n);
    if (forked) cudaEventRecord(evB, s2);

    // CSR build chain on main stream
    k_prep1<<<eb, 256>>>(ei, bt, ew, n, e);
    k_scan_dis<<<nb + ceil_div_i(n, 1024), 1024>>>(n, nb);
    k_scan2<<<1, 1024>>>(nb);
    k_scan3<<<ceil_div_i(n, 256), 256>>>(n, e);
    k_scatter<<<eb, 256>>>(ew, e);

    if (forked) cudaStreamWaitEvent(0, evB, 0);

    // layer 1 aggregate -> layer 2 GEMM -> layer 2 aggregate
    k_agg<<<agg_blocks, 256>>>(b1, n);
    k_gemm_tc<<<gemm_blocks, 256, gemm_smem>>>(x, 1, 1, n);
    k_agg<<<agg_blocks, 256>>>(b2, n);

    // pooling + classifier
    k_poolfinal<<<G, 128>>>(Wl, bl, out, n);
}

// round 8
// speedup vs baseline: 1.8846x; 1.1725x over previous
#include <cuda_runtime.h>
#include <cuda_bf16.h>
#include <cuda_fp16.h>
#include <stdint.h>

// GCN graph classifier: 2x (GCNConv + ReLU) -> global_mean_pool -> Linear
// N=100k, E=1.6M, H=128, G=512, OUT=2.
//
// R8 vs R7 (319us):
//  - GEMM outputs stored as fp16 (g_xwh): aggregation gathers 256B/node
//    instead of 512B -> each LTS-bound agg pass ~halves. fp32 accumulate;
//    agg writes fp32 g_h (exact input for split-bf16 GEMM2 staging).
//  - k_init removed: device globals are zero-init at load; k_scan3 resets
//    g_cnt/g_deg for the next invocation (deterministic steady state).
//  - buffers: GEMM -> g_xwh(fp16); agg -> g_h(fp32); GEMM2 reads g_h,
//    overwrites g_xwh; agg2 reads g_xwh, overwrites g_h; pool reads g_h.

#define HD   128
#define NMAX 100352
#define EMAX 1605632
#define WPAD 136          // padded k-stride (bf16 elems) for smem tiles

__device__ __align__(16) float g_deg[NMAX];          // zero-init; reset by scan3
__device__ __align__(16) float g_dis[NMAX];
__device__ __align__(16) int   g_row[EMAX];
__device__ __align__(16) int   g_col[EMAX];
__device__ __align__(16) int   g_batch[NMAX];
__device__ __align__(16) int   g_cnt[NMAX];          // zero-init; reset by scan3
__device__ __align__(16) int   g_off[NMAX + 1];
__device__ __align__(16) int   g_cur[NMAX];
__device__ __align__(16) int   g_bsum[128];
__device__ __align__(16) int   g_bsumx[128];
__device__ __align__(16) int2  g_edge[EMAX];         // {src row, coef bits}
__device__ __align__(16) __half g_xwh[(size_t)NMAX * HD]; // GEMM out (fp16)
__device__ __align__(16) float  g_h[(size_t)NMAX * HD];   // agg out (fp32)
__device__ __align__(16) __nv_bfloat16 g_Wh[2][HD * HD];  // W^T hi, [n][k]
__device__ __align__(16) __nv_bfloat16 g_Wl[2][HD * HD];  // W^T lo

// ---------------------------------------------------------------------------
// dtype detection (int64 arrays have zero hi-words at odd 32-bit indices)
// ---------------------------------------------------------------------------
__device__ __forceinline__ int detect_ei64(const int* ei32)
{
    int lane = threadIdx.x & 31;
    int v = ei32[2 * lane + 1];
    return __all_sync(0xffffffffu, v == 0);
}

__device__ __forceinline__ int detect_b64(const int* b32, int n)
{
    int lane = threadIdx.x & 31;
    int base = (n > 64) ? ((n - 64) & ~1) : 0;
    int v = b32[base + 2 * lane + 1];
    return __all_sync(0xffffffffu, v == 0);
}

// ---------------------------------------------------------------------------
// prep1: convert edge_index + batch, fused histogram/degree atomics
// (g_deg/g_cnt are zero on entry: load-time init or prior call's scan3)
// ---------------------------------------------------------------------------
__global__ void k_prep1(const void* __restrict__ ei, const void* __restrict__ bt,
                        const float* __restrict__ ew, int n, int e)
{
    __shared__ int s_ei64, s_b64;
    const int* ei32 = (const int*)ei;
    const int* bt32 = (const int*)bt;
    int tid = threadIdx.x;
    if (tid < 32) {
        int r = detect_ei64(ei32);
        if (tid == 0) s_ei64 = r;
    } else if (tid < 64) {
        int r = detect_b64(bt32, n);
        if (tid == 32) s_b64 = r;
    }
    __syncthreads();

    int i = blockIdx.x * blockDim.x + tid;
    if (i < e) {
        int r, c;
        if (s_ei64) {
            const long long* p = (const long long*)ei;
            r = (int)p[i];
            c = (int)p[(size_t)e + i];
        } else {
            r = ei32[i];
            c = ei32[e + i];
        }
        g_row[i] = r;
        g_col[i] = c;
        atomicAdd(&g_deg[c], ew[i]);
        atomicAdd(&g_cnt[c], 1);
    }
    if (i < n)
        g_batch[i] = s_b64 ? (int)((const long long*)bt)[i] : bt32[i];
}

// fused: blocks [0,nb) scan cnt within-block; blocks [nb,..) rsqrt(deg+1)
__global__ void k_scan_dis(int n, int nb)
{
    if ((int)blockIdx.x < nb) {
        __shared__ int s[1024];
        int i = blockIdx.x * 1024 + threadIdx.x;
        int v = (i < n) ? g_cnt[i] : 0;
        s[threadIdx.x] = v;
        __syncthreads();
        for (int off = 1; off < 1024; off <<= 1) {
            int t = 0;
            if ((int)threadIdx.x >= off) t = s[threadIdx.x - off];
            __syncthreads();
            if ((int)threadIdx.x >= off) s[threadIdx.x] += t;
            __syncthreads();
        }
        if (i < n) g_off[i] = s[threadIdx.x];
        if (threadIdx.x == 1023) g_bsum[blockIdx.x] = s[1023];
    } else {
        int i = (blockIdx.x - nb) * 1024 + threadIdx.x;
        if (i < n) g_dis[i] = rsqrtf(g_deg[i] + 1.0f);   // +1 = self-loop
    }
}

__global__ void k_scan2(int nb)
{
    __shared__ int s[1024];
    int t = threadIdx.x;
    int v = (t < nb) ? g_bsum[t] : 0;
    s[t] = v;
    __syncthreads();
    for (int off = 1; off < 1024; off <<= 1) {
        int u = 0;
        if (t >= off) u = s[t - off];
        __syncthreads();
        if (t >= off) s[t] += u;
        __syncthreads();
    }
    if (t < nb) g_bsumx[t] = s[t] - v;
}

// also resets g_cnt/g_deg to zero for the NEXT kernel_launch invocation
__global__ void k_scan3(int n, int e)
{
    int i = blockIdx.x * blockDim.x + threadIdx.x;
    if (i < n) {
        int ex = g_off[i] - g_cnt[i] + g_bsumx[i >> 10];
        g_off[i] = ex;
        g_cur[i] = ex;
        g_cnt[i] = 0;
        g_deg[i] = 0.0f;
    }
    if (i == 0) g_off[n] = e;
}

__global__ void k_scatter(const float* __restrict__ ew, int e)
{
    int i = blockIdx.x * blockDim.x + threadIdx.x;
    if (i >= e) return;
    int r = g_row[i];
    int c = g_col[i];
    float coef = g_dis[r] * ew[i] * g_dis[c];
    int slot = atomicAdd(&g_cur[c], 1);
    g_edge[slot] = make_int2(r, __float_as_int(coef));
}

// ---------------------------------------------------------------------------
// W split: W[k][n] fp32 -> transposed bf16 hi/lo [n][k]
// ---------------------------------------------------------------------------
__global__ void k_wsplit(const float* __restrict__ W1, const float* __restrict__ W2)
{
    int idx = blockIdx.x * blockDim.x + threadIdx.x;
    if (idx >= HD * HD) return;
    int k = idx >> 7, nn = idx & 127;
    float w1 = W1[idx], w2 = W2[idx];
    __nv_bfloat16 h1 = __float2bfloat16(w1);
    __nv_bfloat16 h2 = __float2bfloat16(w2);
    int o = nn * HD + k;
    g_Wh[0][o] = h1;
    g_Wl[0][o] = __float2bfloat16(w1 - __bfloat162float(h1));
    g_Wh[1][o] = h2;
    g_Wl[1][o] = __float2bfloat16(w2 - __bfloat162float(h2));
}

// ---------------------------------------------------------------------------
// tensor-core GEMM: g_xwh[n x 128] = A[n x 128] @ W  (split-bf16, 3 mma terms)
// CTA: 256 thr = 8 warps, tile 128m x 128n, warp tile 64m x 32n, K=128 staged.
// Output stored as fp16 (halves downstream gather traffic).
// ---------------------------------------------------------------------------
#define MMA16816(d, a, b)                                                     \
    asm volatile("mma.sync.aligned.m16n8k16.row.col.f32.bf16.bf16.f32 "       \
                 "{%0,%1,%2,%3}, {%4,%5,%6,%7}, {%8,%9}, {%0,%1,%2,%3};"      \
                 : "+f"((d)[0]), "+f"((d)[1]), "+f"((d)[2]), "+f"((d)[3])     \
                 : "r"((a)[0]), "r"((a)[1]), "r"((a)[2]), "r"((a)[3]),        \
                   "r"((b)[0]), "r"((b)[1]))

__global__ void __launch_bounds__(256) k_gemm_tc(const float* __restrict__ Xin,
                                                 int widx, int useH, int n)
{
    extern __shared__ __align__(16) char smraw[];
    __nv_bfloat16* Ah = (__nv_bfloat16*)smraw;       // [128][WPAD]
    __nv_bfloat16* Al = Ah + 128 * WPAD;
    __nv_bfloat16* Bh = Al + 128 * WPAD;             // W^T [n][k], [128][WPAD]
    __nv_bfloat16* Bl = Bh + 128 * WPAD;

    const float* A = useH ? (const float*)g_h : Xin;
    int tid = threadIdx.x;
    int rowBase = blockIdx.x * 128;

    // stage + split A tile (4096 float4, 16 per thread)
#pragma unroll
    for (int i = 0; i < 16; i++) {
        int f4 = tid + i * 256;
        int r = f4 >> 5;
        int c4 = (f4 & 31) * 4;
        int ar = min(rowBase + r, n - 1);
        float4 v = *(const float4*)(A + (size_t)ar * HD + c4);
        __nv_bfloat16 hx = __float2bfloat16(v.x);
        __nv_bfloat16 hy = __float2bfloat16(v.y);
        __nv_bfloat16 hz = __float2bfloat16(v.z);
        __nv_bfloat16 hw = __float2bfloat16(v.w);
        __nv_bfloat16 lx = __float2bfloat16(v.x - __bfloat162float(hx));
        __nv_bfloat16 ly = __float2bfloat16(v.y - __bfloat162float(hy));
        __nv_bfloat16 lz = __float2bfloat16(v.z - __bfloat162float(hz));
        __nv_bfloat16 lw = __float2bfloat16(v.w - __bfloat162float(hw));
        __nv_bfloat162 h01, h23, l01, l23;
        h01.x = hx; h01.y = hy; h23.x = hz; h23.y = hw;
        l01.x = lx; l01.y = ly; l23.x = lz; l23.y = lw;
        uint2 uh, ul;
        uh.x = *(uint32_t*)&h01; uh.y = *(uint32_t*)&h23;
        ul.x = *(uint32_t*)&l01; ul.y = *(uint32_t*)&l23;
        *(uint2*)&Ah[r * WPAD + c4] = uh;
        *(uint2*)&Al[r * WPAD + c4] = ul;
    }

    // stage W^T tiles
#pragma unroll
    for (int i = 0; i < 8; i++) {
        int idx8 = (tid + i * 256) * 8;
        int r = idx8 >> 7;
        int c = idx8 & 127;
        *(uint4*)&Bh[r * WPAD + c] = *(const uint4*)&g_Wh[widx][idx8];
        *(uint4*)&Bl[r * WPAD + c] = *(const uint4*)&g_Wl[widx][idx8];
    }
    __syncthreads();

    int lane = tid & 31;
    int w = tid >> 5;
    int g = lane >> 2;
    int t = lane & 3;
    int wm0 = (w & 1) * 64;
    int wn0 = (w >> 1) * 32;

    float acc[4][4][4];
#pragma unroll
    for (int mb = 0; mb < 4; mb++)
#pragma unroll
        for (int nb = 0; nb < 4; nb++)
#pragma unroll
            for (int q = 0; q < 4; q++) acc[mb][nb][q] = 0.0f;

#pragma unroll
    for (int ks = 0; ks < 8; ks++) {
        int k0 = ks * 16 + t * 2;
        uint32_t ah[4][4], al[4][4];
#pragma unroll
        for (int mb = 0; mb < 4; mb++) {
            int r0 = wm0 + mb * 16 + g;
            ah[mb][0] = *(const uint32_t*)&Ah[r0 * WPAD + k0];
            ah[mb][1] = *(const uint32_t*)&Ah[(r0 + 8) * WPAD + k0];
            ah[mb][2] = *(const uint32_t*)&Ah[r0 * WPAD + k0 + 8];
            ah[mb][3] = *(const uint32_t*)&Ah[(r0 + 8) * WPAD + k0 + 8];
            al[mb][0] = *(const uint32_t*)&Al[r0 * WPAD + k0];
            al[mb][1] = *(const uint32_t*)&Al[(r0 + 8) * WPAD + k0];
            al[mb][2] = *(const uint32_t*)&Al[r0 * WPAD + k0 + 8];
            al[mb][3] = *(const uint32_t*)&Al[(r0 + 8) * WPAD + k0 + 8];
        }
        uint32_t bh[4][2], bl[4][2];
#pragma unroll
        for (int nb = 0; nb < 4; nb++) {
            int nr = wn0 + nb * 8 + g;
            bh[nb][0] = *(const uint32_t*)&Bh[nr * WPAD + k0];
            bh[nb][1] = *(const uint32_t*)&Bh[nr * WPAD + k0 + 8];
            bl[nb][0] = *(const uint32_t*)&Bl[nr * WPAD + k0];
            bl[nb][1] = *(const uint32_t*)&Bl[nr * WPAD + k0 + 8];
        }
#pragma unroll
        for (int mb = 0; mb < 4; mb++)
#pragma unroll
            for (int nb = 0; nb < 4; nb++) {
                MMA16816(acc[mb][nb], ah[mb], bh[nb]);
                MMA16816(acc[mb][nb], ah[mb], bl[nb]);
                MMA16816(acc[mb][nb], al[mb], bh[nb]);
            }
    }

    // write C as fp16
#pragma unroll
    for (int mb = 0; mb < 4; mb++) {
#pragma unroll
        for (int nb = 0; nb < 4; nb++) {
            int r0 = rowBase + wm0 + mb * 16 + g;
            int c0 = wn0 + nb * 8 + t * 2;
            if (r0 < n) {
                __half2 v0 = __floats2half2_rn(acc[mb][nb][0], acc[mb][nb][1]);
                *(__half2*)&g_xwh[(size_t)r0 * HD + c0] = v0;
            }
            if (r0 + 8 < n) {
                __half2 v1 = __floats2half2_rn(acc[mb][nb][2], acc[mb][nb][3]);
                *(__half2*)&g_xwh[(size_t)(r0 + 8) * HD + c0] = v1;
            }
        }
    }
}

// ---------------------------------------------------------------------------
// aggregation: g_h[node] = relu( dis^2*xwh[node] + sum coef*xwh[src] + b )
// warp per node; lane covers 4 features = one uint2 (4 halves, 8B gather)
// fp16 gathers, fp32 accumulate, fp32 output.
// ---------------------------------------------------------------------------
__device__ __forceinline__ void h4_acc(float4& acc, uint2 u, float c)
{
    float2 f01 = __half22float2(*(__half2*)&u.x);
    float2 f23 = __half22float2(*(__half2*)&u.y);
    acc.x += c * f01.x;
    acc.y += c * f01.y;
    acc.z += c * f23.x;
    acc.w += c * f23.y;
}

__global__ void k_agg(const float* __restrict__ bias, int n)
{
    int gw = (blockIdx.x * blockDim.x + threadIdx.x) >> 5;
    int lane = threadIdx.x & 31;
    if (gw >= n) return;

    const uint2* x2 = (const uint2*)g_xwh;   // 32 uint2 per node
    float sc = g_dis[gw];
    float4 acc = make_float4(0.f, 0.f, 0.f, 0.f);
    h4_acc(acc, x2[(size_t)gw * 32 + lane], sc * sc);

    int p  = g_off[gw];
    int p1 = g_off[gw + 1];
    for (; p + 3 < p1; p += 4) {
        int2 e0 = g_edge[p];
        int2 e1 = g_edge[p + 1];
        int2 e2 = g_edge[p + 2];
        int2 e3 = g_edge[p + 3];
        uint2 u0 = x2[(size_t)e0.x * 32 + lane];
        uint2 u1 = x2[(size_t)e1.x * 32 + lane];
        uint2 u2 = x2[(size_t)e2.x * 32 + lane];
        uint2 u3 = x2[(size_t)e3.x * 32 + lane];
        h4_acc(acc, u0, __int_as_float(e0.y));
        h4_acc(acc, u1, __int_as_float(e1.y));
        h4_acc(acc, u2, __int_as_float(e2.y));
        h4_acc(acc, u3, __int_as_float(e3.y));
    }
    for (; p < p1; p++) {
        int2 e0 = g_edge[p];
        uint2 u0 = x2[(size_t)e0.x * 32 + lane];
        h4_acc(acc, u0, __int_as_float(e0.y));
    }

    float4 bb = ((const float4*)bias)[lane];
    float4 o;
    o.x = fmaxf(acc.x + bb.x, 0.0f);
    o.y = fmaxf(acc.y + bb.y, 0.0f);
    o.z = fmaxf(acc.z + bb.z, 0.0f);
    o.w = fmaxf(acc.w + bb.w, 0.0f);
    ((float4*)g_h)[(size_t)gw * 32 + lane] = o;
}

// ---------------------------------------------------------------------------
// fused pooling + classifier over g_h (binary-search graph bounds)
// ---------------------------------------------------------------------------
__global__ void k_poolfinal(const float* __restrict__ Wl, const float* __restrict__ bl,
                            float* __restrict__ out, int n)
{
    int g = blockIdx.x;
    int f = threadIdx.x;
    __shared__ int sb[2];
    __shared__ float r0[128], r1[128];

    if (f < 2) {
        int target = g + f;
        int lo = 0, hi = n;
        while (lo < hi) {
            int mid = (lo + hi) >> 1;
            if (g_batch[mid] < target) lo = mid + 1; else hi = mid;
        }
        sb[f] = lo;
    }
    __syncthreads();
    int s = sb[0], t = sb[1];

    float acc = 0.0f;
    for (int i = s; i < t; i++) acc += g_h[(size_t)i * HD + f];
    float pooled = acc / fmaxf((float)(t - s), 1.0f);

    r0[f] = pooled * Wl[f * 2 + 0];
    r1[f] = pooled * Wl[f * 2 + 1];
    __syncthreads();
#pragma unroll
    for (int off = 64; off > 0; off >>= 1) {
        if (f < off) { r0[f] += r0[f + off]; r1[f] += r1[f + off]; }
        __syncthreads();
    }
    if (f == 0) {
        out[g * 2 + 0] = r0[0] + bl[0];
        out[g * 2 + 1] = r1[0] + bl[1];
    }
}

// ---------------------------------------------------------------------------
static inline int ceil_div_i(int a, int b) { return (a + b - 1) / b; }

extern "C" void kernel_launch(void* const* d_in, const int* in_sizes, int n_in,
                              void* d_out, int out_size)
{
    (void)n_in;
    const float* x  = (const float*)d_in[0];
    const void*  ei = d_in[1];
    const float* ew = (const float*)d_in[2];
    const void*  bt = d_in[3];
    const float* W1 = (const float*)d_in[4];
    const float* b1 = (const float*)d_in[5];
    const float* W2 = (const float*)d_in[6];
    const float* b2 = (const float*)d_in[7];
    const float* Wl = (const float*)d_in[8];
    const float* bl = (const float*)d_in[9];
    float* out = (float*)d_out;

    int n = in_sizes[0] / HD;
    int e = in_sizes[2];
    int G = out_size / 2;

    int eb = ceil_div_i(e, 256);
    int nb = ceil_div_i(n, 1024);
    int gemm_blocks = ceil_div_i(n, 128);
    int agg_blocks  = ceil_div_i(n, 8);

    int gemm_smem = 4 * 128 * WPAD * (int)sizeof(__nv_bfloat16);  // 139264
    cudaFuncSetAttribute(k_gemm_tc, cudaFuncAttributeMaxDynamicSharedMemorySize,
                         gemm_smem);

    // fork side stream: wsplit + GEMM1 overlap the CSR build chain
    cudaStream_t s2 = 0;
    cudaEvent_t evA = 0, evB = 0;
    bool forked = false;
    if (cudaStreamCreateWithFlags(&s2, cudaStreamNonBlocking) == cudaSuccess &&
        cudaEventCreateWithFlags(&evA, cudaEventDisableTiming) == cudaSuccess &&
        cudaEventCreateWithFlags(&evB, cudaEventDisableTiming) == cudaSuccess) {
        if (cudaEventRecord(evA, 0) == cudaSuccess &&
            cudaStreamWaitEvent(s2, evA, 0) == cudaSuccess)
            forked = true;
    }

    cudaStream_t gs = forked ? s2 : (cudaStream_t)0;
    k_wsplit<<<ceil_div_i(HD * HD, 256), 256, 0, gs>>>(W1, W2);
    k_gemm_tc<<<gemm_blocks, 256, gemm_smem, gs>>>(x, 0, 0, n);
    if (forked) cudaEventRecord(evB, s2);

    // CSR build chain on main stream (g_deg/g_cnt are pre-zeroed)
    k_prep1<<<eb, 256>>>(ei, bt, ew, n, e);
    k_scan_dis<<<nb + ceil_div_i(n, 1024), 1024>>>(n, nb);
    k_scan2<<<1, 1024>>>(nb);
    k_scan3<<<ceil_div_i(n, 256), 256>>>(n, e);
    k_scatter<<<eb, 256>>>(ew, e);

    if (forked) cudaStreamWaitEvent(0, evB, 0);

    // layer 1 aggregate -> layer 2 GEMM -> layer 2 aggregate
    k_agg<<<agg_blocks, 256>>>(b1, n);
    k_gemm_tc<<<gemm_blocks, 256, gemm_smem>>>(x, 1, 1, n);
    k_agg<<<agg_blocks, 256>>>(b2, n);

    // pooling + classifier
    k_poolfinal<<<G, 128>>>(Wl, bl, out, n);
}